// round 15
// baseline (speedup 1.0000x reference)
#include <cuda_runtime.h>
#include <cuda_fp16.h>
#include <math.h>
#include <stdint.h>

#define NN 20000
#define NPAD 20096
#define EE 320000
#define ETOT (EE + NN)
#define INDIM 1536
#define HID 512
#define MIDD 128
#define OUTD 5
#define NHEADS 8

__device__ int   g_deg[NN];
__device__ int   g_rowptr[NN + 1];
__device__ int   g_wofs[NN];
__device__ int   g_col[ETOT];
__device__ __half g_h1h[(size_t)NN * HID];
__device__ __half g_h2h[(size_t)NN * MIDD];
__device__ float g_y2[(size_t)NN * MIDD];
__device__ float g_h3[(size_t)NN * OUTD];
__device__ float g_als[(size_t)NN * NHEADS];
__device__ float g_ald[(size_t)NN * NHEADS];
__device__ __half g_A2[(size_t)NPAD * 2 * INDIM];
__device__ __half g_B2[(size_t)HID * INDIM];
__device__ __half g_B2b[(size_t)MIDD * HID];

__device__ __forceinline__ float leaky(float e) { return e >= 0.f ? e : 0.2f * e; }

__device__ __forceinline__ uint32_t smem_to_u32(const void* smem_ptr) {
    uint32_t addr;
    asm("{ .reg .u64 tmp; cvta.to.shared.u64 tmp, %1; cvt.u32.u64 %0, tmp; }"
        : "=r"(addr) : "l"(smem_ptr));
    return addr;
}
__device__ __forceinline__ void cp_async16(uint32_t dst, const void* src) {
    asm volatile("cp.async.cg.shared.global [%0], [%1], 16;" :: "r"(dst), "l"(src));
}
#define CP_COMMIT() asm volatile("cp.async.commit_group;" ::: "memory")
#define CP_WAIT(N)  asm volatile("cp.async.wait_group %0;" :: "n"(N) : "memory")

__device__ __forceinline__ void ldsm_x4(uint32_t* r, uint32_t addr) {
    asm volatile("ldmatrix.sync.aligned.m8n8.x4.shared.b16 {%0,%1,%2,%3}, [%4];"
                 : "=r"(r[0]), "=r"(r[1]), "=r"(r[2]), "=r"(r[3]) : "r"(addr));
}
__device__ __forceinline__ void mma_f16(float* c, const uint32_t* a, uint32_t b0, uint32_t b1) {
    asm volatile("mma.sync.aligned.m16n8k16.row.col.f32.f16.f16.f32 "
                 "{%0,%1,%2,%3}, {%4,%5,%6,%7}, {%8,%9}, {%0,%1,%2,%3};"
                 : "+f"(c[0]), "+f"(c[1]), "+f"(c[2]), "+f"(c[3])
                 : "r"(a[0]), "r"(a[1]), "r"(a[2]), "r"(a[3]), "r"(b0), "r"(b1));
}

#define NB_TH 15072
#define NB_CD 1329
#define NB_T1 768
#define NB_T2 64
#define NB_PREP (NB_TH + NB_CD + NB_T1 + NB_T2)

__device__ __forceinline__ void trans_block(const float* __restrict__ W, __half* __restrict__ O,
                                            int K, int Nc, int bkx, int bny,
                                            int tx, int ty, float (*t)[33]) {
    int k0 = bkx * 32, n0 = bny * 32;
#pragma unroll
    for (int i = 0; i < 32; i += 8)
        t[ty + i][tx] = W[(size_t)(k0 + ty + i) * Nc + n0 + tx];
    __syncthreads();
#pragma unroll
    for (int i = 0; i < 32; i += 8)
        O[(size_t)(n0 + ty + i) * K + k0 + tx] = __float2half_rn(t[tx][ty + i]);
}

__global__ void __launch_bounds__(256) prep_kernel(
    const float* __restrict__ X, const int* __restrict__ ei,
    const float* __restrict__ W1, const float* __restrict__ W2,
    __half* __restrict__ A2, __half* __restrict__ B2, __half* __restrict__ B2b) {
    __shared__ float t[32][33];
    int b = blockIdx.x, tid = threadIdx.x;
    if (b < NB_TH) {
        int q = b * 256 + tid;
        int K8 = INDIM >> 3;
        if (q >= NPAD * K8) return;
        int m = q / K8;
        float4 v0, v1;
        if (m < NN) {
            v0 = ((const float4*)X)[q * 2];
            v1 = ((const float4*)X)[q * 2 + 1];
        } else {
            v0 = v1 = make_float4(0.f, 0.f, 0.f, 0.f);
        }
        __half2* dh = (__half2*)A2 + q * 4;
        dh[0] = __floats2half2_rn(v0.x, v0.y);
        dh[1] = __floats2half2_rn(v0.z, v0.w);
        dh[2] = __floats2half2_rn(v1.x, v1.y);
        dh[3] = __floats2half2_rn(v1.z, v1.w);
    } else if (b < NB_TH + NB_CD) {
        int e = (b - NB_TH) * 256 + tid;
        if (e >= ETOT) return;
        int dst = (e < EE) ? ei[EE + e] : (e - EE);
        atomicAdd(&g_deg[dst], 1);
    } else if (b < NB_TH + NB_CD + NB_T1) {
        int r = b - NB_TH - NB_CD;
        trans_block(W1, B2, INDIM, HID, r % (INDIM / 32), r / (INDIM / 32),
                    tid & 31, tid >> 5, t);
    } else {
        int r = b - NB_TH - NB_CD - NB_T1;
        trans_block(W2, B2b, HID, MIDD, r % (HID / 32), r / (HID / 32),
                    tid & 31, tid >> 5, t);
    }
}

__global__ void scan_kernel() {
    __shared__ int wsum[32];
    __shared__ int s_carry;
    int tid = threadIdx.x, lane = tid & 31, wid = tid >> 5;
    if (tid == 0) s_carry = 0;
    __syncthreads();
    for (int base = 0; base < NN; base += 1024) {
        int i = base + tid;
        int v = (i < NN) ? g_deg[i] : 0;
        int x = v;
#pragma unroll
        for (int off = 1; off < 32; off <<= 1) {
            int tsh = __shfl_up_sync(0xffffffffu, x, off);
            if (lane >= off) x += tsh;
        }
        if (lane == 31) wsum[wid] = x;
        __syncthreads();
        if (wid == 0) {
            int y = wsum[lane];
#pragma unroll
            for (int off = 1; off < 32; off <<= 1) {
                int tsh = __shfl_up_sync(0xffffffffu, y, off);
                if (lane >= off) y += tsh;
            }
            wsum[lane] = y;
        }
        __syncthreads();
        int wofs = (wid > 0) ? wsum[wid - 1] : 0;
        int excl = x - v + wofs + s_carry;
        if (i < NN) { g_rowptr[i] = excl; g_wofs[i] = excl; }
        int total = wsum[31];
        __syncthreads();
        if (tid == 0) s_carry += total;
        __syncthreads();
    }
    if (tid == 0) g_rowptr[NN] = s_carry;
}

template <typename TOut, int CPHL, int NSTG, int NBX>
__global__ void __launch_bounds__(256, 2) mm_kernel(
    const __half* __restrict__ A, const __half* __restrict__ B,
    TOut* __restrict__ C, int M, int Nc, int K,
    const float* __restrict__ a_s, const float* __restrict__ a_d,
    float* __restrict__ als, float* __restrict__ ald,
    const int* __restrict__ ei, int fillBase) {
    extern __shared__ __align__(128) char smem[];
    constexpr int STG = 2 * 8192;
    const int tid = threadIdx.x;
    int b = blockIdx.x;
    if (b >= fillBase) {
        int e = (b - fillBase) * 256 + tid;
        if (e < ETOT) {
            int src, dst;
            if (e < EE) { src = ei[e]; dst = ei[EE + e]; }
            else        { src = e - EE; dst = e - EE; }
            int pos = atomicAdd(&g_wofs[dst], 1);
            g_col[pos] = src;
        }
        return;
    }
    const int lane = tid & 31, w = tid >> 5;
    const int wm = w & 3, wn = w >> 2;
    const int bx = b % NBX, by = b / NBX;
    const int blockRow = by * 128;
    const int blockCol = bx * 128;
    const int NIT = K / 32;
    uint32_t sbase = smem_to_u32(smem);

    const int lr = tid >> 2;
    const int lc = tid & 3;
    const int lsc = lc ^ ((lr >> 1) & 3);

    auto load_stage = [&](int kt, int s) {
        int kk = kt * 32;
        uint32_t st = sbase + s * STG;
        const __half* Ap = A + (size_t)blockRow * K + kk;
        cp_async16(st + lr * 64 + (lsc << 4),        Ap + (size_t)lr * K + lc * 8);
        cp_async16(st + (lr + 64) * 64 + (lsc << 4), Ap + (size_t)(lr + 64) * K + lc * 8);
        const __half* Bp = B + (size_t)blockCol * K + kk;
        uint32_t sb = st + 8192;
        cp_async16(sb + lr * 64 + (lsc << 4),        Bp + (size_t)lr * K + lc * 8);
        cp_async16(sb + (lr + 64) * 64 + (lsc << 4), Bp + (size_t)(lr + 64) * K + lc * 8);
    };

    float acc[2][8][4];
#pragma unroll
    for (int mi = 0; mi < 2; mi++)
#pragma unroll
        for (int nj = 0; nj < 8; nj++)
#pragma unroll
            for (int q = 0; q < 4; q++) acc[mi][nj][q] = 0.f;

#pragma unroll
    for (int s = 0; s < NSTG - 1; s++) {
        load_stage(s, s);
        CP_COMMIT();
    }

    const int rl = lane & 15, hi = lane >> 4;

    for (int kt = 0; kt < NIT; kt++) {
        CP_WAIT(NSTG - 2);
        __syncthreads();
        if (kt + NSTG - 1 < NIT) load_stage(kt + NSTG - 1, (kt + NSTG - 1) % NSTG);
        CP_COMMIT();
        uint32_t st = sbase + (kt % NSTG) * STG;
        uint32_t sb = st + 8192;
#pragma unroll
        for (int ks = 0; ks < 2; ks++) {
            int ch = ks * 2 + hi;
            uint32_t bfr[4][4];
#pragma unroll
            for (int njp = 0; njp < 4; njp++) {
                int row = wn * 64 + njp * 16 + rl;
                ldsm_x4(bfr[njp], sb + row * 64 + ((ch ^ ((row >> 1) & 3)) << 4));
            }
            uint32_t afr[2][4];
#pragma unroll
            for (int mi = 0; mi < 2; mi++) {
                int row = wm * 32 + mi * 16 + rl;
                ldsm_x4(afr[mi], st + row * 64 + ((ch ^ ((row >> 1) & 3)) << 4));
            }
#pragma unroll
            for (int mi = 0; mi < 2; mi++)
#pragma unroll
                for (int nj = 0; nj < 8; nj++)
                    mma_f16(acc[mi][nj], afr[mi],
                            bfr[nj >> 1][nj & 1], bfr[nj >> 1][2 + (nj & 1)]);
        }
    }

    const int rq = lane >> 2, cq = lane & 3;
#pragma unroll
    for (int mi = 0; mi < 2; mi++) {
#pragma unroll
        for (int h2 = 0; h2 < 2; h2++) {
            int row = blockRow + wm * 32 + mi * 16 + rq + h2 * 8;
            bool valid = row < M;
            if (CPHL == 64) {
                int h = bx * 2 + wn;
                float sA = 0.f, dA = 0.f;
#pragma unroll
                for (int nj = 0; nj < 8; nj++) {
                    int cl = nj * 8 + cq * 2;
                    float vx = acc[mi][nj][2 * h2], vy = acc[mi][nj][2 * h2 + 1];
                    sA = fmaf(vx, a_s[h * 64 + cl], fmaf(vy, a_s[h * 64 + cl + 1], sA));
                    dA = fmaf(vx, a_d[h * 64 + cl], fmaf(vy, a_d[h * 64 + cl + 1], dA));
                }
#pragma unroll
                for (int o = 1; o <= 2; o <<= 1) {
                    sA += __shfl_xor_sync(0xffffffffu, sA, o);
                    dA += __shfl_xor_sync(0xffffffffu, dA, o);
                }
                if (valid && cq == 0) {
                    als[row * NHEADS + h] = sA;
                    ald[row * NHEADS + h] = dA;
                }
            } else if (CPHL == 16) {
                float sA[4] = {0.f, 0.f, 0.f, 0.f}, dA[4] = {0.f, 0.f, 0.f, 0.f};
#pragma unroll
                for (int nj = 0; nj < 8; nj++) {
                    int hl = nj >> 1;
                    int cl = (nj & 1) * 8 + cq * 2;
                    int h = wn * 4 + hl;
                    float vx = acc[mi][nj][2 * h2], vy = acc[mi][nj][2 * h2 + 1];
                    sA[hl] = fmaf(vx, a_s[h * 16 + cl], fmaf(vy, a_s[h * 16 + cl + 1], sA[hl]));
                    dA[hl] = fmaf(vx, a_d[h * 16 + cl], fmaf(vy, a_d[h * 16 + cl + 1], dA[hl]));
                }
#pragma unroll
                for (int hl = 0; hl < 4; hl++) {
#pragma unroll
                    for (int o = 1; o <= 2; o <<= 1) {
                        sA[hl] += __shfl_xor_sync(0xffffffffu, sA[hl], o);
                        dA[hl] += __shfl_xor_sync(0xffffffffu, dA[hl], o);
                    }
                }
                if (valid && cq == 0) {
#pragma unroll
                    for (int hl = 0; hl < 4; hl++) {
                        als[row * NHEADS + wn * 4 + hl] = sA[hl];
                        ald[row * NHEADS + wn * 4 + hl] = dA[hl];
                    }
                }
            }
            if (valid) {
                TOut* Cp = C + (size_t)row * Nc + blockCol + wn * 64 + cq * 2;
#pragma unroll
                for (int nj = 0; nj < 8; nj++) {
                    float vx = acc[mi][nj][2 * h2], vy = acc[mi][nj][2 * h2 + 1];
                    if (sizeof(TOut) == 2)
                        *(__half2*)(Cp + nj * 8) = __floats2half2_rn(vx, vy);
                    else
                        *(float2*)((float*)Cp + nj * 8) = make_float2(vx, vy);
                }
            }
        }
    }
}

__global__ void layer3_kernel(const float* __restrict__ Y, const float* __restrict__ W3,
                              const float* __restrict__ a_s, const float* __restrict__ a_d,
                              float* __restrict__ H3, float* __restrict__ als,
                              float* __restrict__ ald) {
    int w = (blockIdx.x * blockDim.x + threadIdx.x) >> 5;
    int lane = threadIdx.x & 31;
    if (w >= NN) return;
    const float* y = Y + (size_t)w * MIDD;
    float acc[OUTD] = {0.f, 0.f, 0.f, 0.f, 0.f};
#pragma unroll
    for (int kk = 0; kk < MIDD / 32; kk++) {
        int k = lane + kk * 32;
        float v = y[k];
#pragma unroll
        for (int o = 0; o < OUTD; o++)
            acc[o] = fmaf(v, __ldg(W3 + k * OUTD + o), acc[o]);
    }
#pragma unroll
    for (int o = 0; o < OUTD; o++)
#pragma unroll
        for (int off = 16; off; off >>= 1)
            acc[o] += __shfl_xor_sync(0xffffffffu, acc[o], off);
    if (lane == 0) {
        float s = 0.f, d = 0.f;
#pragma unroll
        for (int o = 0; o < OUTD; o++) {
            H3[(size_t)w * OUTD + o] = acc[o];
            s = fmaf(acc[o], a_s[o], s);
            d = fmaf(acc[o], a_d[o], d);
        }
        als[w] = s;
        ald[w] = d;
    }
}

// ---------------- GAT aggregation: warp-per-node, single-pass softmax ----------------
template <int CPH, bool SPLIT>
__global__ void __launch_bounds__(128) aggregate_kernel(
    const __half* __restrict__ Hf, const float* __restrict__ als, const float* __restrict__ ald,
    const float* __restrict__ bias, const float* __restrict__ gamma, const float* __restrict__ beta,
    const float* __restrict__ mean, const float* __restrict__ var,
    float* __restrict__ outp, __half* __restrict__ outh) {
    constexpr int HC = NHEADS * CPH;
    constexpr int ACC = HC / 32;
    constexpr int NH2 = ACC / 2;
    constexpr int CAP = 64;
    __shared__ float s_alpha[4][CAP][NHEADS];
    __shared__ int   s_col[4][CAP];
    __shared__ float s_dinv[4][NHEADS];

    int tid = threadIdx.x, lane = tid & 31, wid = tid >> 5;
    int n = blockIdx.x * 4 + wid;
    if (SPLIT) {
        if (n >= NPAD) return;
        if (n >= NN) {
            uint4 z = make_uint4(0, 0, 0, 0);
            uint4* p = (uint4*)(outh + (size_t)n * HC + lane * 16);
            p[0] = z; p[1] = z;
            return;
        }
    } else {
        if (n >= NN) return;
    }
    int r0 = g_rowptr[n], r1 = g_rowptr[n + 1];
    int deg = r1 - r0;
    int dcap = deg < CAP ? deg : CAP;

    float4 al0 = *(const float4*)(ald + (size_t)n * NHEADS);
    float4 al1 = *(const float4*)(ald + (size_t)n * NHEADS + 4);
    float d0 = 0.f, d1 = 0.f, d2 = 0.f, d3 = 0.f, d4 = 0.f, d5 = 0.f, d6 = 0.f, d7 = 0.f;
    for (int j = lane; j < deg; j += 32) {
        int s = g_col[r0 + j];
        float4 a0 = *(const float4*)(als + (size_t)s * NHEADS);
        float4 a1 = *(const float4*)(als + (size_t)s * NHEADS + 4);
        float e0 = __expf(leaky(a0.x + al0.x));
        float e1 = __expf(leaky(a0.y + al0.y));
        float e2 = __expf(leaky(a0.z + al0.z));
        float e3 = __expf(leaky(a0.w + al0.w));
        float e4 = __expf(leaky(a1.x + al1.x));
        float e5 = __expf(leaky(a1.y + al1.y));
        float e6 = __expf(leaky(a1.z + al1.z));
        float e7 = __expf(leaky(a1.w + al1.w));
        d0 += e0; d1 += e1; d2 += e2; d3 += e3;
        d4 += e4; d5 += e5; d6 += e6; d7 += e7;
        if (j < CAP) {
            s_col[wid][j] = s;
            *(float4*)&s_alpha[wid][j][0] = make_float4(e0, e1, e2, e3);
            *(float4*)&s_alpha[wid][j][4] = make_float4(e4, e5, e6, e7);
        }
    }
#pragma unroll
    for (int o = 16; o; o >>= 1) {
        d0 += __shfl_xor_sync(0xffffffffu, d0, o);
        d1 += __shfl_xor_sync(0xffffffffu, d1, o);
        d2 += __shfl_xor_sync(0xffffffffu, d2, o);
        d3 += __shfl_xor_sync(0xffffffffu, d3, o);
        d4 += __shfl_xor_sync(0xffffffffu, d4, o);
        d5 += __shfl_xor_sync(0xffffffffu, d5, o);
        d6 += __shfl_xor_sync(0xffffffffu, d6, o);
        d7 += __shfl_xor_sync(0xffffffffu, d7, o);
    }
    d0 = 1.0f / (d0 + 1e-16f); d1 = 1.0f / (d1 + 1e-16f);
    d2 = 1.0f / (d2 + 1e-16f); d3 = 1.0f / (d3 + 1e-16f);
    d4 = 1.0f / (d4 + 1e-16f); d5 = 1.0f / (d5 + 1e-16f);
    d6 = 1.0f / (d6 + 1e-16f); d7 = 1.0f / (d7 + 1e-16f);
    __syncwarp();
    for (int j = lane; j < dcap; j += 32) {
        float4 e03 = *(float4*)&s_alpha[wid][j][0];
        float4 e47 = *(float4*)&s_alpha[wid][j][4];
        *(float4*)&s_alpha[wid][j][0] = make_float4(e03.x * d0, e03.y * d1, e03.z * d2, e03.w * d3);
        *(float4*)&s_alpha[wid][j][4] = make_float4(e47.x * d4, e47.y * d5, e47.z * d6, e47.w * d7);
    }
    if (lane == 0) {
        s_dinv[wid][0] = d0; s_dinv[wid][1] = d1; s_dinv[wid][2] = d2; s_dinv[wid][3] = d3;
        s_dinv[wid][4] = d4; s_dinv[wid][5] = d5; s_dinv[wid][6] = d6; s_dinv[wid][7] = d7;
    }
    __syncwarp();

    const int c0 = lane * ACC;
    const int hh = lane >> 2;
    float acc[ACC];
#pragma unroll
    for (int a = 0; a < ACC; a++) acc[a] = 0.f;

    int j = 0;
    for (; j + 4 <= dcap; j += 4) {
        uint32_t wv[4][NH2];
        float a4[4];
#pragma unroll
        for (int u = 0; u < 4; u++) {
            int s = s_col[wid][j + u];
            const __half* hp = Hf + (size_t)s * HC + c0;
            if (ACC == 16) {
                uint4 t0 = *(const uint4*)hp;
                uint4 t1 = *(const uint4*)(hp + 8);
                wv[u][0] = t0.x; wv[u][1] = t0.y; wv[u][2] = t0.z; wv[u][3] = t0.w;
                wv[u][4] = t1.x; wv[u][5] = t1.y; wv[u][6] = t1.z; wv[u][7] = t1.w;
            } else {
                uint2 t0 = *(const uint2*)hp;
                wv[u][0] = t0.x; wv[u][1] = t0.y;
            }
            a4[u] = s_alpha[wid][j + u][hh];
        }
        __half2 hacc[NH2];
#pragma unroll
        for (int k = 0; k < NH2; k++) hacc[k] = __floats2half2_rn(0.f, 0.f);
#pragma unroll
        for (int u = 0; u < 4; u++) {
            __half2 ah = __float2half2_rn(a4[u]);
#pragma unroll
            for (int k = 0; k < NH2; k++)
                hacc[k] = __hfma2(ah, *(const __half2*)&wv[u][k], hacc[k]);
        }
#pragma unroll
        for (int k = 0; k < NH2; k++) {
            float2 f = __half22float2(hacc[k]);
            acc[2 * k] += f.x;
            acc[2 * k + 1] += f.y;
        }
    }
    for (; j < dcap; j++) {
        int s = s_col[wid][j];
        float al = s_alpha[wid][j][hh];
        const __half* hp = Hf + (size_t)s * HC + c0;
#pragma unroll
        for (int k = 0; k < NH2; k++) {
            float2 v = __half22float2(*(const __half2*)(hp + 2 * k));
            acc[2 * k]     = fmaf(al, v.x, acc[2 * k]);
            acc[2 * k + 1] = fmaf(al, v.y, acc[2 * k + 1]);
        }
    }
    for (; j < deg; j++) {
        int s = g_col[r0 + j];
        float al = __expf(leaky(als[(size_t)s * NHEADS + hh] + ald[(size_t)n * NHEADS + hh]))
                   * s_dinv[wid][hh];
        const __half* hp = Hf + (size_t)s * HC + c0;
#pragma unroll
        for (int k = 0; k < NH2; k++) {
            float2 v = __half22float2(*(const __half2*)(hp + 2 * k));
            acc[2 * k]     = fmaf(al, v.x, acc[2 * k]);
            acc[2 * k + 1] = fmaf(al, v.y, acc[2 * k + 1]);
        }
    }

    float v[ACC];
#pragma unroll
    for (int a = 0; a < ACC; a++) {
        int c = c0 + a;
        float t = acc[a] + bias[c];
        t = fmaxf(t, 0.f);
        v[a] = (t - mean[c]) * rsqrtf(var[c] + 1e-5f) * gamma[c] + beta[c];
    }
    if (SPLIT) {
        uint4 pk0, pk1;
#pragma unroll
        for (int k = 0; k < 4; k++)
            ((__half2*)&pk0)[k] = __floats2half2_rn(v[2 * k], v[2 * k + 1]);
#pragma unroll
        for (int k = 0; k < 4; k++)
            ((__half2*)&pk1)[k] = __floats2half2_rn(v[8 + 2 * k], v[9 + 2 * k]);
        uint4* p = (uint4*)(outh + (size_t)n * HC + c0);
        p[0] = pk0; p[1] = pk1;
    } else {
#pragma unroll
        for (int a = 0; a < ACC; a += 4)
            *(float4*)(outp + (size_t)n * HC + c0 + a) =
                make_float4(v[a], v[a + 1], v[a + 2], v[a + 3]);
    }
}

__global__ void aggregate3_kernel(const float* __restrict__ Hf, const float* __restrict__ als,
                                  const float* __restrict__ ald, const float* __restrict__ bias,
                                  float* __restrict__ outp) {
    int w = (blockIdx.x * blockDim.x + threadIdx.x) >> 5;
    int lane = threadIdx.x & 31;
    if (w >= NN) return;
    int r0 = g_rowptr[w], r1 = g_rowptr[w + 1];
    float aldv = ald[w];

    float ds = 0.f, a0 = 0.f, a1 = 0.f, a2 = 0.f, a3 = 0.f, a4 = 0.f;
    for (int j = r0 + lane; j < r1; j += 32) {
        int s = g_col[j];
        float ex = __expf(leaky(als[s] + aldv));
        ds += ex;
        const float* hr = Hf + (size_t)s * OUTD;
        a0 = fmaf(ex, hr[0], a0);
        a1 = fmaf(ex, hr[1], a1);
        a2 = fmaf(ex, hr[2], a2);
        a3 = fmaf(ex, hr[3], a3);
        a4 = fmaf(ex, hr[4], a4);
    }
#pragma unroll
    for (int o = 16; o; o >>= 1) {
        ds += __shfl_xor_sync(0xffffffffu, ds, o);
        a0 += __shfl_xor_sync(0xffffffffu, a0, o);
        a1 += __shfl_xor_sync(0xffffffffu, a1, o);
        a2 += __shfl_xor_sync(0xffffffffu, a2, o);
        a3 += __shfl_xor_sync(0xffffffffu, a3, o);
        a4 += __shfl_xor_sync(0xffffffffu, a4, o);
    }
    if (lane == 0) {
        float inv = 1.0f / (ds + 1e-16f);
        float v[5];
        v[0] = a0 * inv + bias[0];
        v[1] = a1 * inv + bias[1];
        v[2] = a2 * inv + bias[2];
        v[3] = a3 * inv + bias[3];
        v[4] = a4 * inv + bias[4];
        float mx = v[0];
#pragma unroll
        for (int o = 1; o < 5; o++) mx = fmaxf(mx, v[o]);
        float se = 0.f;
#pragma unroll
        for (int o = 0; o < 5; o++) se += __expf(v[o] - mx);
        float ls = mx + logf(se);
#pragma unroll
        for (int o = 0; o < 5; o++) outp[(size_t)w * 5 + o] = v[o] - ls;
    }
}

extern "C" void kernel_launch(void* const* d_in, const int* in_sizes, int n_in,
                              void* d_out, int out_size) {
    const float* x   = (const float*)d_in[0];
    const int*   ei  = (const int*)d_in[1];
    const float* W1  = (const float*)d_in[2];
    const float* as1 = (const float*)d_in[3];
    const float* ad1 = (const float*)d_in[4];
    const float* b1  = (const float*)d_in[5];
    const float* W2  = (const float*)d_in[6];
    const float* as2 = (const float*)d_in[7];
    const float* ad2 = (const float*)d_in[8];
    const float* b2  = (const float*)d_in[9];
    const float* W3  = (const float*)d_in[10];
    const float* as3 = (const float*)d_in[11];
    const float* ad3 = (const float*)d_in[12];
    const float* b3  = (const float*)d_in[13];
    const float* g1  = (const float*)d_in[14];
    const float* be1 = (const float*)d_in[15];
    const float* m1  = (const float*)d_in[16];
    const float* v1  = (const float*)d_in[17];
    const float* g2  = (const float*)d_in[18];
    const float* be2 = (const float*)d_in[19];
    const float* m2  = (const float*)d_in[20];
    const float* v2  = (const float*)d_in[21];
    float* out = (float*)d_out;

    float *p_y2, *p_h3, *p_als, *p_ald;
    int* p_deg;
    __half *p_A2, *p_B2, *p_B2b, *p_h1h, *p_h2h;
    cudaGetSymbolAddress((void**)&p_h1h, g_h1h);
    cudaGetSymbolAddress((void**)&p_h2h, g_h2h);
    cudaGetSymbolAddress((void**)&p_y2, g_y2);
    cudaGetSymbolAddress((void**)&p_h3, g_h3);
    cudaGetSymbolAddress((void**)&p_als, g_als);
    cudaGetSymbolAddress((void**)&p_ald, g_ald);
    cudaGetSymbolAddress((void**)&p_deg, g_deg);
    cudaGetSymbolAddress((void**)&p_A2, g_A2);
    cudaGetSymbolAddress((void**)&p_B2, g_B2);
    cudaGetSymbolAddress((void**)&p_B2b, g_B2b);

    const int SMEM1 = 4 * 2 * 8192;
    const int SMEM2 = 3 * 2 * 8192;
    cudaFuncSetAttribute((const void*)mm_kernel<__half, 64, 4, 4>,
                         cudaFuncAttributeMaxDynamicSharedMemorySize, SMEM1);
    cudaFuncSetAttribute((const void*)mm_kernel<__half, 16, 3, 1>,
                         cudaFuncAttributeMaxDynamicSharedMemorySize, SMEM2);

    const int MTILES = NPAD / 128;
    const int MM1_BLOCKS = 4 * MTILES;
    const int FILL_BLOCKS = (ETOT + 255) / 256;

    cudaMemsetAsync(p_deg, 0, NN * sizeof(int), 0);
    prep_kernel<<<NB_PREP, 256>>>(x, ei, W1, W2, p_A2, p_B2, p_B2b);
    scan_kernel<<<1, 1024>>>();

    mm_kernel<__half, 64, 4, 4><<<MM1_BLOCKS + FILL_BLOCKS, 256, SMEM1>>>(
        p_A2, p_B2, p_h1h, NN, HID, INDIM, as1, ad1, p_als, p_ald, ei, MM1_BLOCKS);
    aggregate_kernel<64, true><<<NPAD / 4, 128>>>(
        p_h1h, p_als, p_ald, b1, g1, be1, m1, v1, nullptr, p_A2);

    mm_kernel<__half, 16, 3, 1><<<1 * MTILES, 256, SMEM2>>>(
        p_A2, p_B2b, p_h2h, NN, MIDD, HID, as2, ad2, p_als, p_ald, nullptr, 1 * MTILES);
    aggregate_kernel<16, false><<<(NN + 3) / 4, 128>>>(
        p_h2h, p_als, p_ald, b2, g2, be2, m2, v2, p_y2, nullptr);

    layer3_kernel<<<(NN * 32 + 255) / 256, 256>>>(p_y2, W3, as3, ad3, p_h3, p_als, p_ald);
    aggregate3_kernel<<<(NN * 32 + 255) / 256, 256>>>(p_h3, p_als, p_ald, b3, out);
}

// round 16
// speedup vs baseline: 1.1615x; 1.1615x over previous
#include <cuda_runtime.h>
#include <cuda_fp16.h>
#include <math.h>
#include <stdint.h>

#define NN 20000
#define NPAD 20096
#define EE 320000
#define ETOT (EE + NN)
#define INDIM 1536
#define HID 512
#define MIDD 128
#define OUTD 5
#define NHEADS 8

__device__ int   g_deg[NN];
__device__ int   g_rowptr[NN + 1];
__device__ int   g_wofs[NN];
__device__ int   g_col[ETOT];
__device__ __half g_h1h[(size_t)NN * HID];
__device__ float g_h2[(size_t)NN * MIDD];
__device__ float g_y2[(size_t)NN * MIDD];
__device__ float g_h3[(size_t)NN * OUTD];
__device__ float g_als[(size_t)NN * NHEADS];
__device__ float g_ald[(size_t)NN * NHEADS];
__device__ __half g_A2[(size_t)NPAD * 2 * INDIM];
__device__ __half g_B2[(size_t)HID * INDIM];
__device__ __half g_B2b[(size_t)MIDD * HID];

__device__ __forceinline__ float leaky(float e) { return e >= 0.f ? e : 0.2f * e; }

__device__ __forceinline__ uint32_t smem_to_u32(const void* smem_ptr) {
    uint32_t addr;
    asm("{ .reg .u64 tmp; cvta.to.shared.u64 tmp, %1; cvt.u32.u64 %0, tmp; }"
        : "=r"(addr) : "l"(smem_ptr));
    return addr;
}
__device__ __forceinline__ void cp_async16(uint32_t dst, const void* src) {
    asm volatile("cp.async.cg.shared.global [%0], [%1], 16;" :: "r"(dst), "l"(src));
}
#define CP_COMMIT() asm volatile("cp.async.commit_group;" ::: "memory")
#define CP_WAIT(N)  asm volatile("cp.async.wait_group %0;" :: "n"(N) : "memory")

__device__ __forceinline__ void ldsm_x4(uint32_t* r, uint32_t addr) {
    asm volatile("ldmatrix.sync.aligned.m8n8.x4.shared.b16 {%0,%1,%2,%3}, [%4];"
                 : "=r"(r[0]), "=r"(r[1]), "=r"(r[2]), "=r"(r[3]) : "r"(addr));
}
__device__ __forceinline__ void mma_f16(float* c, const uint32_t* a, uint32_t b0, uint32_t b1) {
    asm volatile("mma.sync.aligned.m16n8k16.row.col.f32.f16.f16.f32 "
                 "{%0,%1,%2,%3}, {%4,%5,%6,%7}, {%8,%9}, {%0,%1,%2,%3};"
                 : "+f"(c[0]), "+f"(c[1]), "+f"(c[2]), "+f"(c[3])
                 : "r"(a[0]), "r"(a[1]), "r"(a[2]), "r"(a[3]), "r"(b0), "r"(b1));
}

#define NB_TH 15072
#define NB_CD 1329
#define NB_T1 768
#define NB_T2 64
#define NB_PREP (NB_TH + NB_CD + NB_T1 + NB_T2)

__device__ __forceinline__ void trans_block(const float* __restrict__ W, __half* __restrict__ O,
                                            int K, int Nc, int bkx, int bny,
                                            int tx, int ty, float (*t)[33]) {
    int k0 = bkx * 32, n0 = bny * 32;
#pragma unroll
    for (int i = 0; i < 32; i += 8)
        t[ty + i][tx] = W[(size_t)(k0 + ty + i) * Nc + n0 + tx];
    __syncthreads();
#pragma unroll
    for (int i = 0; i < 32; i += 8)
        O[(size_t)(n0 + ty + i) * K + k0 + tx] = __float2half_rn(t[tx][ty + i]);
}

__global__ void __launch_bounds__(256) prep_kernel(
    const float* __restrict__ X, const int* __restrict__ ei,
    const float* __restrict__ W1, const float* __restrict__ W2,
    __half* __restrict__ A2, __half* __restrict__ B2, __half* __restrict__ B2b) {
    __shared__ float t[32][33];
    int b = blockIdx.x, tid = threadIdx.x;
    if (b < NB_TH) {
        int q = b * 256 + tid;
        int K8 = INDIM >> 3;
        if (q >= NPAD * K8) return;
        int m = q / K8;
        float4 v0, v1;
        if (m < NN) {
            v0 = ((const float4*)X)[q * 2];
            v1 = ((const float4*)X)[q * 2 + 1];
        } else {
            v0 = v1 = make_float4(0.f, 0.f, 0.f, 0.f);
        }
        __half2* dh = (__half2*)A2 + q * 4;
        dh[0] = __floats2half2_rn(v0.x, v0.y);
        dh[1] = __floats2half2_rn(v0.z, v0.w);
        dh[2] = __floats2half2_rn(v1.x, v1.y);
        dh[3] = __floats2half2_rn(v1.z, v1.w);
    } else if (b < NB_TH + NB_CD) {
        int e = (b - NB_TH) * 256 + tid;
        if (e >= ETOT) return;
        int dst = (e < EE) ? ei[EE + e] : (e - EE);
        atomicAdd(&g_deg[dst], 1);
    } else if (b < NB_TH + NB_CD + NB_T1) {
        int r = b - NB_TH - NB_CD;
        trans_block(W1, B2, INDIM, HID, r % (INDIM / 32), r / (INDIM / 32),
                    tid & 31, tid >> 5, t);
    } else {
        int r = b - NB_TH - NB_CD - NB_T1;
        trans_block(W2, B2b, HID, MIDD, r % (HID / 32), r / (HID / 32),
                    tid & 31, tid >> 5, t);
    }
}

__global__ void scan_kernel() {
    __shared__ int wsum[32];
    __shared__ int s_carry;
    int tid = threadIdx.x, lane = tid & 31, wid = tid >> 5;
    if (tid == 0) s_carry = 0;
    __syncthreads();
    for (int base = 0; base < NN; base += 1024) {
        int i = base + tid;
        int v = (i < NN) ? g_deg[i] : 0;
        int x = v;
#pragma unroll
        for (int off = 1; off < 32; off <<= 1) {
            int tsh = __shfl_up_sync(0xffffffffu, x, off);
            if (lane >= off) x += tsh;
        }
        if (lane == 31) wsum[wid] = x;
        __syncthreads();
        if (wid == 0) {
            int y = wsum[lane];
#pragma unroll
            for (int off = 1; off < 32; off <<= 1) {
                int tsh = __shfl_up_sync(0xffffffffu, y, off);
                if (lane >= off) y += tsh;
            }
            wsum[lane] = y;
        }
        __syncthreads();
        int wofs = (wid > 0) ? wsum[wid - 1] : 0;
        int excl = x - v + wofs + s_carry;
        if (i < NN) { g_rowptr[i] = excl; g_wofs[i] = excl; }
        int total = wsum[31];
        __syncthreads();
        if (tid == 0) s_carry += total;
        __syncthreads();
    }
    if (tid == 0) g_rowptr[NN] = s_carry;
}

template <typename TOut, int CPHL, int NSTG, int NBX>
__global__ void __launch_bounds__(256, 2) mm_kernel(
    const __half* __restrict__ A, const __half* __restrict__ B,
    TOut* __restrict__ C, int M, int Nc, int K,
    const float* __restrict__ a_s, const float* __restrict__ a_d,
    float* __restrict__ als, float* __restrict__ ald,
    const int* __restrict__ ei, int fillBase) {
    extern __shared__ __align__(128) char smem[];
    constexpr int STG = 2 * 8192;
    const int tid = threadIdx.x;
    int b = blockIdx.x;
    if (b >= fillBase) {
        int e = (b - fillBase) * 256 + tid;
        if (e < ETOT) {
            int src, dst;
            if (e < EE) { src = ei[e]; dst = ei[EE + e]; }
            else        { src = e - EE; dst = e - EE; }
            int pos = atomicAdd(&g_wofs[dst], 1);
            g_col[pos] = src;
        }
        return;
    }
    const int lane = tid & 31, w = tid >> 5;
    const int wm = w & 3, wn = w >> 2;
    const int bx = b % NBX, by = b / NBX;
    const int blockRow = by * 128;
    const int blockCol = bx * 128;
    const int NIT = K / 32;
    uint32_t sbase = smem_to_u32(smem);

    const int lr = tid >> 2;
    const int lc = tid & 3;
    const int lsc = lc ^ ((lr >> 1) & 3);

    auto load_stage = [&](int kt, int s) {
        int kk = kt * 32;
        uint32_t st = sbase + s * STG;
        const __half* Ap = A + (size_t)blockRow * K + kk;
        cp_async16(st + lr * 64 + (lsc << 4),        Ap + (size_t)lr * K + lc * 8);
        cp_async16(st + (lr + 64) * 64 + (lsc << 4), Ap + (size_t)(lr + 64) * K + lc * 8);
        const __half* Bp = B + (size_t)blockCol * K + kk;
        uint32_t sb = st + 8192;
        cp_async16(sb + lr * 64 + (lsc << 4),        Bp + (size_t)lr * K + lc * 8);
        cp_async16(sb + (lr + 64) * 64 + (lsc << 4), Bp + (size_t)(lr + 64) * K + lc * 8);
    };

    float acc[2][8][4];
#pragma unroll
    for (int mi = 0; mi < 2; mi++)
#pragma unroll
        for (int nj = 0; nj < 8; nj++)
#pragma unroll
            for (int q = 0; q < 4; q++) acc[mi][nj][q] = 0.f;

#pragma unroll
    for (int s = 0; s < NSTG - 1; s++) {
        load_stage(s, s);
        CP_COMMIT();
    }

    const int rl = lane & 15, hi = lane >> 4;

    for (int kt = 0; kt < NIT; kt++) {
        CP_WAIT(NSTG - 2);
        __syncthreads();
        if (kt + NSTG - 1 < NIT) load_stage(kt + NSTG - 1, (kt + NSTG - 1) % NSTG);
        CP_COMMIT();
        uint32_t st = sbase + (kt % NSTG) * STG;
        uint32_t sb = st + 8192;
#pragma unroll
        for (int ks = 0; ks < 2; ks++) {
            int ch = ks * 2 + hi;
            uint32_t bfr[4][4];
#pragma unroll
            for (int njp = 0; njp < 4; njp++) {
                int row = wn * 64 + njp * 16 + rl;
                ldsm_x4(bfr[njp], sb + row * 64 + ((ch ^ ((row >> 1) & 3)) << 4));
            }
            uint32_t afr[2][4];
#pragma unroll
            for (int mi = 0; mi < 2; mi++) {
                int row = wm * 32 + mi * 16 + rl;
                ldsm_x4(afr[mi], st + row * 64 + ((ch ^ ((row >> 1) & 3)) << 4));
            }
#pragma unroll
            for (int mi = 0; mi < 2; mi++)
#pragma unroll
                for (int nj = 0; nj < 8; nj++)
                    mma_f16(acc[mi][nj], afr[mi],
                            bfr[nj >> 1][nj & 1], bfr[nj >> 1][2 + (nj & 1)]);
        }
    }

    const int rq = lane >> 2, cq = lane & 3;
#pragma unroll
    for (int mi = 0; mi < 2; mi++) {
#pragma unroll
        for (int h2 = 0; h2 < 2; h2++) {
            int row = blockRow + wm * 32 + mi * 16 + rq + h2 * 8;
            bool valid = row < M;
            if (CPHL == 64) {
                int h = bx * 2 + wn;
                float sA = 0.f, dA = 0.f;
#pragma unroll
                for (int nj = 0; nj < 8; nj++) {
                    int cl = nj * 8 + cq * 2;
                    float vx = acc[mi][nj][2 * h2], vy = acc[mi][nj][2 * h2 + 1];
                    sA = fmaf(vx, a_s[h * 64 + cl], fmaf(vy, a_s[h * 64 + cl + 1], sA));
                    dA = fmaf(vx, a_d[h * 64 + cl], fmaf(vy, a_d[h * 64 + cl + 1], dA));
                }
#pragma unroll
                for (int o = 1; o <= 2; o <<= 1) {
                    sA += __shfl_xor_sync(0xffffffffu, sA, o);
                    dA += __shfl_xor_sync(0xffffffffu, dA, o);
                }
                if (valid && cq == 0) {
                    als[row * NHEADS + h] = sA;
                    ald[row * NHEADS + h] = dA;
                }
            } else if (CPHL == 16) {
                float sA[4] = {0.f, 0.f, 0.f, 0.f}, dA[4] = {0.f, 0.f, 0.f, 0.f};
#pragma unroll
                for (int nj = 0; nj < 8; nj++) {
                    int hl = nj >> 1;
                    int cl = (nj & 1) * 8 + cq * 2;
                    int h = wn * 4 + hl;
                    float vx = acc[mi][nj][2 * h2], vy = acc[mi][nj][2 * h2 + 1];
                    sA[hl] = fmaf(vx, a_s[h * 16 + cl], fmaf(vy, a_s[h * 16 + cl + 1], sA[hl]));
                    dA[hl] = fmaf(vx, a_d[h * 16 + cl], fmaf(vy, a_d[h * 16 + cl + 1], dA[hl]));
                }
#pragma unroll
                for (int hl = 0; hl < 4; hl++) {
#pragma unroll
                    for (int o = 1; o <= 2; o <<= 1) {
                        sA[hl] += __shfl_xor_sync(0xffffffffu, sA[hl], o);
                        dA[hl] += __shfl_xor_sync(0xffffffffu, dA[hl], o);
                    }
                }
                if (valid && cq == 0) {
#pragma unroll
                    for (int hl = 0; hl < 4; hl++) {
                        als[row * NHEADS + wn * 4 + hl] = sA[hl];
                        ald[row * NHEADS + wn * 4 + hl] = dA[hl];
                    }
                }
            }
            if (valid) {
                TOut* Cp = C + (size_t)row * Nc + blockCol + wn * 64 + cq * 2;
#pragma unroll
                for (int nj = 0; nj < 8; nj++) {
                    float vx = acc[mi][nj][2 * h2], vy = acc[mi][nj][2 * h2 + 1];
                    if (sizeof(TOut) == 2)
                        *(__half2*)(Cp + nj * 8) = __floats2half2_rn(vx, vy);
                    else
                        *(float2*)((float*)Cp + nj * 8) = make_float2(vx, vy);
                }
            }
        }
    }
}

__global__ void layer3_kernel(const float* __restrict__ Y, const float* __restrict__ W3,
                              const float* __restrict__ a_s, const float* __restrict__ a_d,
                              float* __restrict__ H3, float* __restrict__ als,
                              float* __restrict__ ald) {
    int w = (blockIdx.x * blockDim.x + threadIdx.x) >> 5;
    int lane = threadIdx.x & 31;
    if (w >= NN) return;
    const float* y = Y + (size_t)w * MIDD;
    float acc[OUTD] = {0.f, 0.f, 0.f, 0.f, 0.f};
#pragma unroll
    for (int kk = 0; kk < MIDD / 32; kk++) {
        int k = lane + kk * 32;
        float v = y[k];
#pragma unroll
        for (int o = 0; o < OUTD; o++)
            acc[o] = fmaf(v, __ldg(W3 + k * OUTD + o), acc[o]);
    }
#pragma unroll
    for (int o = 0; o < OUTD; o++)
#pragma unroll
        for (int off = 16; off; off >>= 1)
            acc[o] += __shfl_xor_sync(0xffffffffu, acc[o], off);
    if (lane == 0) {
        float s = 0.f, d = 0.f;
#pragma unroll
        for (int o = 0; o < OUTD; o++) {
            H3[(size_t)w * OUTD + o] = acc[o];
            s = fmaf(acc[o], a_s[o], s);
            d = fmaf(acc[o], a_d[o], d);
        }
        als[w] = s;
        ald[w] = d;
    }
}

// ---------------- GAT aggregation (HT==8), block-per-node (round-13 structure) --------
template <int HT, int CPH, int NT, bool SPLIT, typename TIn>
__global__ void __launch_bounds__(NT) aggregate_kernel(
    const TIn* __restrict__ Hf, const float* __restrict__ als, const float* __restrict__ ald,
    const float* __restrict__ bias, const float* __restrict__ gamma, const float* __restrict__ beta,
    const float* __restrict__ mean, const float* __restrict__ var,
    float* __restrict__ outp, __half* __restrict__ outh) {
    constexpr int HC = HT * CPH;
    constexpr int ACCN = HC / NT;
    constexpr int CAP = 128;
    static_assert(HT == 8 && NT == 128, "layout assumption");
    __shared__ float s_alpha[CAP][HT];
    __shared__ int   s_col[CAP];
    __shared__ float s_d[HT], s_ald[HT];

    int n = blockIdx.x;
    int tid = threadIdx.x, lane = tid & 31, wid = tid >> 5;
    if (SPLIT && n >= NN) {
        int idx = (n - NN) * NT * 8 + tid * 8;
        if (idx < (NPAD - NN) * HC)
            *(uint4*)(outh + (size_t)NN * HC + idx) = make_uint4(0, 0, 0, 0);
        return;
    }
    int r0 = g_rowptr[n], r1 = g_rowptr[n + 1];
    int deg = r1 - r0;
    int dcap = deg < CAP ? deg : CAP;
    if (tid < HT) s_ald[tid] = ald[n * HT + tid];
    for (int j = tid; j < dcap; j += NT) s_col[j] = g_col[r0 + j];
    __syncthreads();

    // single-pass softmax: warp wid owns heads {2*wid, 2*wid+1}
    {
        int h0 = 2 * wid;
        float2 aldv = *(const float2*)(ald + (size_t)n * HT + h0);
        float ald0 = aldv.x, ald1 = aldv.y;
        float d0 = 0.f, d1 = 0.f;
        for (int j = lane; j < deg; j += 32) {
            int s = (j < CAP) ? s_col[j] : g_col[r0 + j];
            float2 a = *(const float2*)(als + (size_t)s * HT + h0);
            float e0 = __expf(leaky(a.x + ald0));
            float e1 = __expf(leaky(a.y + ald1));
            d0 += e0; d1 += e1;
            if (j < CAP) { s_alpha[j][h0] = e0; s_alpha[j][h0 + 1] = e1; }
        }
#pragma unroll
        for (int o = 16; o; o >>= 1) {
            d0 += __shfl_xor_sync(0xffffffffu, d0, o);
            d1 += __shfl_xor_sync(0xffffffffu, d1, o);
        }
        d0 = 1.0f / (d0 + 1e-16f);
        d1 = 1.0f / (d1 + 1e-16f);
        for (int j = lane; j < dcap; j += 32) {
            s_alpha[j][h0] *= d0;
            s_alpha[j][h0 + 1] *= d1;
        }
        if (lane == 0) { s_d[h0] = d0; s_d[h0 + 1] = d1; }
    }
    __syncthreads();

    // main accumulation, 8-way pipelined (thread = ACCN contiguous channels)
    const int c0 = tid * ACCN;
    const int hh = c0 / CPH;
    float acc[ACCN];
#pragma unroll
    for (int a = 0; a < ACCN; a++) acc[a] = 0.f;

    int j = 0;
    if (sizeof(TIn) == 2) {
        const __half* Hp = (const __half*)Hf;
        for (; j + 8 <= dcap; j += 8) {
            uint2 w8[8]; float a8[8];
#pragma unroll
            for (int u = 0; u < 8; u++) {
                int s = s_col[j + u];
                w8[u] = *(const uint2*)(Hp + (size_t)s * HC + c0);
                a8[u] = s_alpha[j + u][hh];
            }
            __half2 hc0 = __floats2half2_rn(0.f, 0.f);
            __half2 hc1 = __floats2half2_rn(0.f, 0.f);
#pragma unroll
            for (int u = 0; u < 8; u++) {
                __half2 ah = __float2half2_rn(a8[u]);
                hc0 = __hfma2(ah, *(const __half2*)&w8[u].x, hc0);
                hc1 = __hfma2(ah, *(const __half2*)&w8[u].y, hc1);
            }
            float2 f0 = __half22float2(hc0);
            float2 f1 = __half22float2(hc1);
            acc[0] += f0.x; acc[1] += f0.y;
            acc[2] += f1.x; acc[3] += f1.y;
        }
        for (; j < dcap; j++) {
            int s = s_col[j];
            float a0 = s_alpha[j][hh];
            uint2 w0 = *(const uint2*)(Hp + (size_t)s * HC + c0);
#pragma unroll
            for (int q = 0; q < 2; q++) {
                float2 v = __half22float2(*(__half2*)(q ? &w0.y : &w0.x));
                acc[2 * q]     = fmaf(a0, v.x, acc[2 * q]);
                acc[2 * q + 1] = fmaf(a0, v.y, acc[2 * q + 1]);
            }
        }
    } else {
        const float* Hp = (const float*)Hf;
        for (; j + 8 <= dcap; j += 8) {
            float v8[8];
#pragma unroll
            for (int u = 0; u < 8; u++) v8[u] = Hp[(size_t)s_col[j + u] * HC + c0];
#pragma unroll
            for (int u = 0; u < 8; u++) acc[0] = fmaf(s_alpha[j + u][hh], v8[u], acc[0]);
        }
        for (; j < dcap; j++)
            acc[0] = fmaf(s_alpha[j][hh], Hp[(size_t)s_col[j] * HC + c0], acc[0]);
    }
    for (; j < deg; j++) {
        int s = g_col[r0 + j];
        float alpha = __expf(leaky(als[(size_t)s * HT + hh] + s_ald[hh])) * s_d[hh];
        if (sizeof(TIn) == 2) {
            const __half* Hp = (const __half*)Hf;
            uint2 w0 = *(const uint2*)(Hp + (size_t)s * HC + c0);
#pragma unroll
            for (int q = 0; q < 2; q++) {
                float2 v = __half22float2(*(__half2*)(q ? &w0.y : &w0.x));
                acc[2 * q]     = fmaf(alpha, v.x, acc[2 * q]);
                acc[2 * q + 1] = fmaf(alpha, v.y, acc[2 * q + 1]);
            }
        } else {
            acc[0] = fmaf(alpha, ((const float*)Hf)[(size_t)s * HC + c0], acc[0]);
        }
    }

    float v[ACCN];
#pragma unroll
    for (int a = 0; a < ACCN; a++) {
        int c = c0 + a;
        float t = acc[a] + bias[c];
        t = fmaxf(t, 0.f);
        v[a] = (t - mean[c]) * rsqrtf(var[c] + 1e-5f) * gamma[c] + beta[c];
    }
    if (SPLIT) {
        // ACCN == 4: pack 4 halves into one 8B store
        uint2 pk;
        ((__half2*)&pk)[0] = __floats2half2_rn(v[0], v[1]);
        ((__half2*)&pk)[1] = __floats2half2_rn(v[2], v[3]);
        *(uint2*)(outh + (size_t)n * HC + c0) = pk;
    } else {
#pragma unroll
        for (int a = 0; a < ACCN; a++)
            outp[(size_t)n * HC + c0 + a] = v[a];
    }
}

__global__ void aggregate3_kernel(const float* __restrict__ Hf, const float* __restrict__ als,
                                  const float* __restrict__ ald, const float* __restrict__ bias,
                                  float* __restrict__ outp) {
    int w = (blockIdx.x * blockDim.x + threadIdx.x) >> 5;
    int lane = threadIdx.x & 31;
    if (w >= NN) return;
    int r0 = g_rowptr[w], r1 = g_rowptr[w + 1];
    float aldv = ald[w];

    float ds = 0.f, a0 = 0.f, a1 = 0.f, a2 = 0.f, a3 = 0.f, a4 = 0.f;
    for (int j = r0 + lane; j < r1; j += 32) {
        int s = g_col[j];
        float ex = __expf(leaky(als[s] + aldv));
        ds += ex;
        const float* hr = Hf + (size_t)s * OUTD;
        a0 = fmaf(ex, hr[0], a0);
        a1 = fmaf(ex, hr[1], a1);
        a2 = fmaf(ex, hr[2], a2);
        a3 = fmaf(ex, hr[3], a3);
        a4 = fmaf(ex, hr[4], a4);
    }
#pragma unroll
    for (int o = 16; o; o >>= 1) {
        ds += __shfl_xor_sync(0xffffffffu, ds, o);
        a0 += __shfl_xor_sync(0xffffffffu, a0, o);
        a1 += __shfl_xor_sync(0xffffffffu, a1, o);
        a2 += __shfl_xor_sync(0xffffffffu, a2, o);
        a3 += __shfl_xor_sync(0xffffffffu, a3, o);
        a4 += __shfl_xor_sync(0xffffffffu, a4, o);
    }
    if (lane == 0) {
        float inv = 1.0f / (ds + 1e-16f);
        float v[5];
        v[0] = a0 * inv + bias[0];
        v[1] = a1 * inv + bias[1];
        v[2] = a2 * inv + bias[2];
        v[3] = a3 * inv + bias[3];
        v[4] = a4 * inv + bias[4];
        float mx = v[0];
#pragma unroll
        for (int o = 1; o < 5; o++) mx = fmaxf(mx, v[o]);
        float se = 0.f;
#pragma unroll
        for (int o = 0; o < 5; o++) se += __expf(v[o] - mx);
        float ls = mx + logf(se);
#pragma unroll
        for (int o = 0; o < 5; o++) outp[(size_t)w * 5 + o] = v[o] - ls;
    }
}

extern "C" void kernel_launch(void* const* d_in, const int* in_sizes, int n_in,
                              void* d_out, int out_size) {
    const float* x   = (const float*)d_in[0];
    const int*   ei  = (const int*)d_in[1];
    const float* W1  = (const float*)d_in[2];
    const float* as1 = (const float*)d_in[3];
    const float* ad1 = (const float*)d_in[4];
    const float* b1  = (const float*)d_in[5];
    const float* W2  = (const float*)d_in[6];
    const float* as2 = (const float*)d_in[7];
    const float* ad2 = (const float*)d_in[8];
    const float* b2  = (const float*)d_in[9];
    const float* W3  = (const float*)d_in[10];
    const float* as3 = (const float*)d_in[11];
    const float* ad3 = (const float*)d_in[12];
    const float* b3  = (const float*)d_in[13];
    const float* g1  = (const float*)d_in[14];
    const float* be1 = (const float*)d_in[15];
    const float* m1  = (const float*)d_in[16];
    const float* v1  = (const float*)d_in[17];
    const float* g2  = (const float*)d_in[18];
    const float* be2 = (const float*)d_in[19];
    const float* m2  = (const float*)d_in[20];
    const float* v2  = (const float*)d_in[21];
    float* out = (float*)d_out;

    float *p_h2, *p_y2, *p_h3, *p_als, *p_ald;
    int* p_deg;
    __half *p_A2, *p_B2, *p_B2b, *p_h1h;
    cudaGetSymbolAddress((void**)&p_h1h, g_h1h);
    cudaGetSymbolAddress((void**)&p_h2, g_h2);
    cudaGetSymbolAddress((void**)&p_y2, g_y2);
    cudaGetSymbolAddress((void**)&p_h3, g_h3);
    cudaGetSymbolAddress((void**)&p_als, g_als);
    cudaGetSymbolAddress((void**)&p_ald, g_ald);
    cudaGetSymbolAddress((void**)&p_deg, g_deg);
    cudaGetSymbolAddress((void**)&p_A2, g_A2);
    cudaGetSymbolAddress((void**)&p_B2, g_B2);
    cudaGetSymbolAddress((void**)&p_B2b, g_B2b);

    const int SMEM1 = 4 * 2 * 8192;
    const int SMEM2 = 3 * 2 * 8192;
    cudaFuncSetAttribute((const void*)mm_kernel<__half, 64, 4, 4>,
                         cudaFuncAttributeMaxDynamicSharedMemorySize, SMEM1);
    cudaFuncSetAttribute((const void*)mm_kernel<float, 16, 3, 1>,
                         cudaFuncAttributeMaxDynamicSharedMemorySize, SMEM2);

    const int MTILES = NPAD / 128;
    const int MM1_BLOCKS = 4 * MTILES;
    const int FILL_BLOCKS = (ETOT + 255) / 256;

    cudaMemsetAsync(p_deg, 0, NN * sizeof(int), 0);
    prep_kernel<<<NB_PREP, 256>>>(x, ei, W1, W2, p_A2, p_B2, p_B2b);
    scan_kernel<<<1, 1024>>>();

    mm_kernel<__half, 64, 4, 4><<<MM1_BLOCKS + FILL_BLOCKS, 256, SMEM1>>>(
        p_A2, p_B2, p_h1h, NN, HID, INDIM, as1, ad1, p_als, p_ald, ei, MM1_BLOCKS);
    aggregate_kernel<8, 64, 128, true, __half><<<NN + 48, 128>>>(
        p_h1h, p_als, p_ald, b1, g1, be1, m1, v1, nullptr, p_A2);

    mm_kernel<float, 16, 3, 1><<<1 * MTILES, 256, SMEM2>>>(
        p_A2, p_B2b, p_h2, NN, MIDD, HID, as2, ad2, p_als, p_ald, nullptr, 1 * MTILES);
    aggregate_kernel<8, 16, 128, false, float><<<NN, 128>>>(
        p_h2, p_als, p_ald, b2, g2, be2, m2, v2, p_y2, nullptr);

    layer3_kernel<<<(NN * 32 + 255) / 256, 256>>>(p_y2, W3, as3, ad3, p_h3, p_als, p_ald);
    aggregate3_kernel<<<(NN * 32 + 255) / 256, 256>>>(p_h3, p_als, p_ald, b3, out);
}